// round 4
// baseline (speedup 1.0000x reference)
#include <cuda_runtime.h>
#include <math.h>

#define BN 64
#define CN 512
#define HW 784
#define HW4 196
#define CSEG 64
#define R_TOT (BN * CN)
#define GRID_AP 444
#define FEPS 1e-12f

// ---------------- scratch (static __device__, no allocation) ----------------
__device__ float g_Y[3][BN * HW];         // 3-buffer rotation of Wm^T z (unnormalized)
__device__ float g_vec[3][BN * CN];       // 0: u4 (raw z4), 1: v (raw AAT x1), 2: x2 (unit)
__device__ float g_nrm2[8][BN];           // 0:||x0||^2, 1..4:||z_k||^2
__device__ float g_sc[8][BN];             // 0:num5 1:den5 2:num6 3:den6 4:largest 5:invw

// ---------------- init: zero Y0,Y1 + accumulators ----------------
__global__ void k_init() {
    int g = blockIdx.x * blockDim.x + threadIdx.x;
    int n = gridDim.x * blockDim.x;
    for (int i = g; i < BN * HW; i += n) { g_Y[0][i] = 0.f; g_Y[1][i] = 0.f; }
    for (int i = g; i < 8 * BN; i += n) ((float*)g_nrm2)[i] = 0.f;
    for (int i = g; i < 8 * BN; i += n) ((float*)g_sc)[i] = 0.f;
}

// ---------------- ||x0||^2 per batch ----------------
__global__ void k_n0(const float* __restrict__ x0) {
    __shared__ float red[16];
    int b = blockIdx.x, t = threadIdx.x;       // 512 threads = C
    float v = x0[b * CN + t];
    float s = v * v;
    #pragma unroll
    for (int o = 16; o; o >>= 1) s += __shfl_xor_sync(0xffffffffu, s, o);
    if ((t & 31) == 0) red[t >> 5] = s;
    __syncthreads();
    if (t < 16) {
        s = red[t];
        #pragma unroll
        for (int o = 8; o; o >>= 1) s += __shfl_xor_sync(0xffffu, s, o);
        if (t == 0) g_nrm2[0][b] = s;
    }
}

// ---------------- S1: Y0[b][d] += sum_{c in seg} A[b][c][d] * x0[b][c] -------
__global__ void k_s1(const float4* __restrict__ A4, const float* __restrict__ x0in) {
    int b = blockIdx.x >> 3, seg = blockIdx.x & 7;
    int t = threadIdx.x;                       // 224 threads, 196 active
    if (t >= HW4) return;
    const float* xp = x0in + b * CN + seg * CSEG;
    const float4* Ab = A4 + (size_t)(b * CN + seg * CSEG) * HW4 + t;
    float ax = 0.f, ay = 0.f, az = 0.f, aw = 0.f;
    #pragma unroll 8
    for (int c = 0; c < CSEG; c++) {
        float xv = xp[c];
        float4 a = Ab[(size_t)c * HW4];
        ax += a.x * xv; ay += a.y * xv; az += a.z * xv; aw += a.w * xv;
    }
    float* y = &g_Y[0][b * HW + t * 4];
    atomicAdd(y + 0, ax); atomicAdd(y + 1, ay);
    atomicAdd(y + 2, az); atomicAdd(y + 3, aw);
}

// ---------------- fused apply: z = Wm ys ; Yout += Wm^T z ; reductions -------
// mode 0: la1 = sum z^2 -> g_nrm2[a1]; optional z store to g_vec[zSel]
// mode 1: store v=z to g_vec[zSel]; num5 += z*x1, den5 += x1^2 (x1 = u4*invu4)
// mode 2: ys = (Y[2] - largest*invu4*Y[1])*invw ; num6 += z*x2, den6 += x2^2
__global__ void __launch_bounds__(256, 3) k_ap(
        const float4* __restrict__ A4, int inSel, int outSel, int zeroSel,
        int mode, int nsIn, int zSel, int a1, int a2)
{
    __shared__ float ys[HW];
    __shared__ float yw[8][HW];
    int t = threadIdx.x, warp = t >> 5, lane = t & 31;   // 256 threads
    int blk = blockIdx.x, G = gridDim.x;

    // zero the spare buffer (safe: nothing else touches it this launch)
    if (zeroSel >= 0) {
        float* Z = g_Y[zeroSel];
        int per = (BN * HW + G - 1) / G;
        int base = blk * per;
        int end = base + per; if (end > BN * HW) end = BN * HW;
        for (int i = base + t; i < end; i += 256) Z[i] = 0.f;
    }

    int rs = (int)((long long)blk * R_TOT / G);
    int re = (int)((long long)(blk + 1) * R_TOT / G);

    while (rs < re) {
        int b = rs >> 9;
        int cs = rs & (CN - 1);
        int ce = re - (b << 9); if (ce > CN) ce = CN;

        __syncthreads();    // protect ys/yw reuse across sub-ranges
        // --- build ys for batch b ---
        if (mode < 2) {
            const float* Yin = g_Y[inSel] + b * HW;
            float s = 1.0f / fmaxf(sqrtf(g_nrm2[nsIn][b]), FEPS);
            for (int i = t; i < HW; i += 256) ys[i] = Yin[i] * s;
        } else {
            float invu4 = 1.0f / fmaxf(sqrtf(g_nrm2[4][b]), FEPS);
            float f4 = g_sc[4][b] * invu4;
            float invw = g_sc[5][b];
            for (int i = t; i < HW; i += 256)
                ys[i] = (g_Y[2][b * HW + i] - f4 * g_Y[1][b * HW + i]) * invw;
        }
        __syncthreads();

        const float4* ys4 = (const float4*)ys;
        bool k6 = (lane < 4);
        float4 acc[7];
        #pragma unroll
        for (int k = 0; k < 7; k++) acc[k] = make_float4(0.f, 0.f, 0.f, 0.f);
        float la1 = 0.f, la2 = 0.f;
        float invu4 = (mode == 1) ? 1.0f / fmaxf(sqrtf(g_nrm2[nsIn][b]), FEPS) : 1.0f;

        for (int c = cs + warp; c < ce; c += 8) {
            const float4* Ar = A4 + (size_t)(b * CN + c) * HW4;
            // --- dot: z[c] = A[c,:] . ys ---
            float d0 = 0.f, d1 = 0.f, d2 = 0.f, d3 = 0.f;
            #pragma unroll
            for (int k = 0; k < 6; k++) {
                int idx = k * 32 + lane;
                float4 a = Ar[idx]; float4 y = ys4[idx];
                d0 += a.x * y.x; d1 += a.y * y.y;
                d2 += a.z * y.z; d3 += a.w * y.w;
            }
            if (k6) {
                int idx = 192 + lane;
                float4 a = Ar[idx]; float4 y = ys4[idx];
                d0 += a.x * y.x; d1 += a.y * y.y;
                d2 += a.z * y.z; d3 += a.w * y.w;
            }
            float z = (d0 + d1) + (d2 + d3);
            #pragma unroll
            for (int o = 16; o; o >>= 1) z += __shfl_xor_sync(0xffffffffu, z, o);

            // --- axpy: reload row from L1 (just touched) ---
            #pragma unroll
            for (int k = 0; k < 6; k++) {
                float4 a = Ar[k * 32 + lane];
                acc[k].x += z * a.x; acc[k].y += z * a.y;
                acc[k].z += z * a.z; acc[k].w += z * a.w;
            }
            if (k6) {
                float4 a = Ar[192 + lane];
                acc[6].x += z * a.x; acc[6].y += z * a.y;
                acc[6].z += z * a.z; acc[6].w += z * a.w;
            }
            if (lane == 0) {
                if (mode == 0) {
                    if (zSel >= 0) g_vec[zSel][b * CN + c] = z;
                    la1 += z * z;
                } else if (mode == 1) {
                    g_vec[zSel][b * CN + c] = z;
                    float xc = g_vec[0][b * CN + c] * invu4;
                    la1 += z * xc; la2 += xc * xc;
                } else {
                    float xc = g_vec[2][b * CN + c];
                    la1 += z * xc; la2 += xc * xc;
                }
            }
        }

        // --- flush scalar reductions (per batch) ---
        if (lane == 0) {
            if (mode == 0) {
                atomicAdd(&g_nrm2[a1][b], la1);
            } else {
                atomicAdd(&g_sc[a1][b], la1);
                atomicAdd(&g_sc[a2][b], la2);
            }
        }

        // --- flush Yout (per batch): block-reduce 8 warps then atomicAdd ---
        if (outSel >= 0) {
            float4* yo = (float4*)yw[warp];
            #pragma unroll
            for (int k = 0; k < 6; k++) yo[k * 32 + lane] = acc[k];
            if (k6) yo[192 + lane] = acc[6];
            __syncthreads();
            float* Yout = g_Y[outSel] + b * HW;
            for (int i = t; i < HW; i += 256) {
                float s = 0.f;
                #pragma unroll
                for (int w = 0; w < 8; w++) s += yw[w][i];
                atomicAdd(&Yout[i], s);
            }
        }
        rs = (b << 9) + ce;
    }
}

// ---------------- K5: largest, w = v - largest*x1, x2 = w/||w||, invw --------
__global__ void k_k5() {
    __shared__ float red[16];
    __shared__ float wtot;
    int b = blockIdx.x, t = threadIdx.x;       // 512 threads
    float inv4 = 1.0f / fmaxf(sqrtf(g_nrm2[4][b]), FEPS);
    float largest = g_sc[0][b] / g_sc[1][b];
    float x1c = g_vec[0][b * CN + t] * inv4;
    float w = g_vec[1][b * CN + t] - largest * x1c;
    float s = w * w;
    #pragma unroll
    for (int o = 16; o; o >>= 1) s += __shfl_xor_sync(0xffffffffu, s, o);
    if ((t & 31) == 0) red[t >> 5] = s;
    __syncthreads();
    if (t < 16) {
        s = red[t];
        #pragma unroll
        for (int o = 8; o; o >>= 1) s += __shfl_xor_sync(0xffffu, s, o);
        if (t == 0) wtot = s;
    }
    __syncthreads();
    float invw = 1.0f / fmaxf(sqrtf(wtot), FEPS);
    g_vec[2][b * CN + t] = w * invw;
    if (t == 0) { g_sc[4][b] = largest; g_sc[5][b] = invw; }
}

// ---------------- final: penalty = sum_b (largest/smallest - 1)^2 / B --------
__global__ void k_fin(float* __restrict__ out) {
    __shared__ float red[2];
    int t = threadIdx.x;                        // 64 threads
    float largest = g_sc[4][t];
    float tmp = g_sc[2][t] / g_sc[3][t] - largest;
    float smallest = tmp + largest;
    float r = largest / smallest - 1.0f;
    float p = r * r;
    #pragma unroll
    for (int o = 16; o; o >>= 1) p += __shfl_xor_sync(0xffffffffu, p, o);
    if ((t & 31) == 0) red[t >> 5] = p;
    __syncthreads();
    if (t == 0) out[0] = (red[0] + red[1]) / (float)BN;
}

// ---------------- launch ----------------
extern "C" void kernel_launch(void* const* d_in, const int* in_sizes, int n_in,
                              void* d_out, int out_size) {
    const float* A  = (const float*)d_in[0];
    const float* x0 = (const float*)d_in[1];
    if (n_in >= 2 && in_sizes[0] < in_sizes[1]) {   // safety: A is the big one
        const float* t = A; A = x0; x0 = t;
    }
    const float4* A4 = (const float4*)A;
    float* out = (float*)d_out;
    (void)out_size;

    k_init<<<128, 512>>>();
    k_n0<<<BN, CN>>>(x0);

    // Y0 = Wm^T x0 (unnormalized) -> g_Y[0]         [1 A-sweep]
    k_s1<<<BN * 8, 224>>>(A4, x0);

    //        in  out zero mode ns  z  a1 a2
    k_ap<<<GRID_AP, 256>>>(A4, 0, 1, 2, 0, 0, -1, 1, 0);  // z1, Y1->B1
    k_ap<<<GRID_AP, 256>>>(A4, 1, 2, 0, 0, 1, -1, 2, 0);  // z2, Y2->B2
    k_ap<<<GRID_AP, 256>>>(A4, 2, 0, 1, 0, 2, -1, 3, 0);  // z3, Y3->B0
    k_ap<<<GRID_AP, 256>>>(A4, 0, 1, 2, 0, 3,  0, 4, 0);  // z4=u4 store, Y4->B1
    k_ap<<<GRID_AP, 256>>>(A4, 1, 2, 0, 1, 4,  1, 0, 1);  // v=AAT x1, Y5->B2

    k_k5<<<BN, CN>>>();                                   // largest, x2, invw

    k_ap<<<GRID_AP, 256>>>(A4, 0, -1, -1, 2, 0, -1, 2, 3); // t=AAT x2; num6,den6

    k_fin<<<1, 64>>>(out);
}

// round 6
// speedup vs baseline: 1.4420x; 1.4420x over previous
#include <cuda_runtime.h>
#include <math.h>

#define BN 64
#define CN 512
#define HW 784
#define HW4 196
#define NSEG 8
#define CSEG 64
#define FEPS 1e-12f

// ---------------- scratch (static __device__, no allocation) ----------------
__device__ float g_Ya[NSEG * BN * HW];    // ping: Y0, Y2, Y4 (= Wm^T z, unnormalized)
__device__ float g_Yb[NSEG * BN * HW];    // pong: Y1, Y3, Y5
__device__ float g_vec[3][BN * CN];       // 0: u4 (raw z4), 1: v (raw AAT x1), 2: x2 (unit)
__device__ float g_nrm2[8][BN];           // 0:||x0||^2, 1..4:||z_k||^2
__device__ float g_sc[8][BN];             // 0:num5 1:den5 2:num6 3:den6 4:largest 5:invw

// L2 evict_last policy: pin A (103MB) in L2 (126MB) across the 7 sweeps.
__device__ __forceinline__ unsigned long long mk_policy() {
    unsigned long long pol;
    asm("createpolicy.fractional.L2::evict_last.b64 %0, 1.0;" : "=l"(pol));
    return pol;
}
__device__ __forceinline__ float4 ldg_el(const float4* p, unsigned long long pol) {
    float4 r;
    asm volatile("ld.global.nc.L2::cache_hint.v4.f32 {%0,%1,%2,%3}, [%4], %5;"
                 : "=f"(r.x), "=f"(r.y), "=f"(r.z), "=f"(r.w) : "l"(p), "l"(pol));
    return r;
}

// ---------------- init: zero accumulators ----------------
__global__ void k_init() {
    int t = threadIdx.x;                       // 512 threads
    if (t < 8 * BN) ((float*)g_nrm2)[t] = 0.0f;
    if (t < 8 * BN) ((float*)g_sc)[t] = 0.0f;
}

// ---------------- ||x0||^2 per batch ----------------
__global__ void k_n0(const float* __restrict__ x0) {
    __shared__ float red[16];
    int b = blockIdx.x, t = threadIdx.x;       // 512 threads = C
    float v = x0[b * CN + t];
    float s = v * v;
    #pragma unroll
    for (int o = 16; o; o >>= 1) s += __shfl_xor_sync(0xffffffffu, s, o);
    if ((t & 31) == 0) red[t >> 5] = s;
    __syncthreads();
    if (t < 16) {
        s = red[t];
        #pragma unroll
        for (int o = 8; o; o >>= 1) s += __shfl_xor_sync(0xffffu, s, o);
        if (t == 0) g_nrm2[0][b] = s;
    }
}

// ---------------- S1 (only for x0): Y0[seg][b][d] = sum_{c in seg} A[b][c][d]*x0[b][c]
__global__ void k_s1(const float4* __restrict__ A4, const float* __restrict__ x0in) {
    int b = blockIdx.x >> 3, seg = blockIdx.x & 7;
    int t = threadIdx.x;                       // 224 threads, 196 active
    if (t >= HW4) return;
    unsigned long long pol = mk_policy();
    const float* xp = x0in + b * CN + seg * CSEG;
    const float4* Ab = A4 + (size_t)(b * CN + seg * CSEG) * HW4 + t;
    float ax = 0.f, ay = 0.f, az = 0.f, aw = 0.f;
    #pragma unroll 8
    for (int c = 0; c < CSEG; c++) {
        float xv = xp[c];
        float4 a = ldg_el(Ab + (size_t)c * HW4, pol);
        ax += a.x * xv; ay += a.y * xv; az += a.z * xv; aw += a.w * xv;
    }
    float4 r; r.x = ax; r.y = ay; r.z = az; r.w = aw;
    ((float4*)g_Ya)[(seg * BN + b) * HW4 + t] = r;
}

// ---------------- fused apply: z = Wm * ys ; Ynext = Wm^T z ; reductions -----
// mode 0: reduction ||z||^2 -> g_nrm2[a1]; optional z store
// mode 1: store v=z; num5 += z*x1, den5 += x1^2   (x1 = u4 * invu4)
// mode 2: ys = (sumYb - largest*invu4*sumYa)*invw ; num6 += z*x2, den6 += x2^2
__global__ void __launch_bounds__(256, 2) k_ap(
        const float4* __restrict__ A4, int yinSel, int youtSel, int zSel,
        int mode, int nsIn, int a1, int a2)
{
    __shared__ float ys[HW];
    __shared__ float yw[8][HW];
    __shared__ float r1s[8], r2s[8];
    int b = blockIdx.x >> 3, seg = blockIdx.x & 7;
    int t = threadIdx.x, warp = t >> 5, lane = t & 31;   // 256 threads
    unsigned long long pol = mk_policy();

    // --- build ys in shared ---
    if (mode < 2) {
        const float* Yin = yinSel ? g_Yb : g_Ya;
        float s = 1.0f / fmaxf(sqrtf(g_nrm2[nsIn][b]), FEPS);
        for (int i = t; i < HW; i += 256) {
            float acc = 0.f;
            #pragma unroll
            for (int sg = 0; sg < NSEG; sg++) acc += Yin[(sg * BN + b) * HW + i];
            ys[i] = acc * s;
        }
    } else {
        float invu4 = 1.0f / fmaxf(sqrtf(g_nrm2[4][b]), FEPS);
        float largest = g_sc[4][b];
        float invw = g_sc[5][b];
        float f4 = largest * invu4;
        for (int i = t; i < HW; i += 256) {
            float a5 = 0.f, a4 = 0.f;
            #pragma unroll
            for (int sg = 0; sg < NSEG; sg++) {
                a5 += g_Yb[(sg * BN + b) * HW + i];
                a4 += g_Ya[(sg * BN + b) * HW + i];
            }
            ys[i] = (a5 - f4 * a4) * invw;
        }
    }
    __syncthreads();

    const float4* ys4 = (const float4*)ys;
    bool k6 = (lane < 4);
    float4 acc[7];
    #pragma unroll
    for (int k = 0; k < 7; k++) acc[k] = make_float4(0.f, 0.f, 0.f, 0.f);
    float la1 = 0.f, la2 = 0.f;
    float invu4 = (mode == 1) ? 1.0f / fmaxf(sqrtf(g_nrm2[nsIn][b]), FEPS) : 1.0f;
    float* zout = (zSel >= 0) ? &g_vec[zSel][0] : (float*)0;

    int c0 = seg * CSEG + warp * 8;
    const float4* Ar0 = A4 + (size_t)(b * CN + c0) * HW4;

    // --- software-pipelined rows: cur/nxt double buffer (MLP ~14/warp) ---
    float4 cur[7], nxt[7];
    #pragma unroll
    for (int k = 0; k < 6; k++) cur[k] = ldg_el(Ar0 + k * 32 + lane, pol);
    cur[6] = k6 ? ldg_el(Ar0 + 192 + lane, pol) : make_float4(0.f, 0.f, 0.f, 0.f);

    #pragma unroll
    for (int r = 0; r < 8; r++) {
        // issue next row's loads before consuming current row
        if (r < 7) {
            const float4* Arn = Ar0 + (size_t)(r + 1) * HW4;
            #pragma unroll
            for (int k = 0; k < 6; k++) nxt[k] = ldg_el(Arn + k * 32 + lane, pol);
            nxt[6] = k6 ? ldg_el(Arn + 192 + lane, pol) : make_float4(0.f, 0.f, 0.f, 0.f);
        }
        // dot with cur
        float d0 = 0.f, d1 = 0.f, d2 = 0.f, d3 = 0.f;
        #pragma unroll
        for (int k = 0; k < 6; k++) {
            float4 y = ys4[k * 32 + lane];
            d0 += cur[k].x * y.x; d1 += cur[k].y * y.y;
            d2 += cur[k].z * y.z; d3 += cur[k].w * y.w;
        }
        if (k6) {
            float4 y = ys4[192 + lane];
            d0 += cur[6].x * y.x; d1 += cur[6].y * y.y;
            d2 += cur[6].z * y.z; d3 += cur[6].w * y.w;
        }
        float z = (d0 + d1) + (d2 + d3);
        #pragma unroll
        for (int o = 16; o; o >>= 1) z += __shfl_xor_sync(0xffffffffu, z, o);

        // axpy into Ynext accumulators (row still in registers)
        #pragma unroll
        for (int k = 0; k < 7; k++) {
            acc[k].x += z * cur[k].x; acc[k].y += z * cur[k].y;
            acc[k].z += z * cur[k].z; acc[k].w += z * cur[k].w;
        }
        if (lane == 0) {
            int c = c0 + r;
            if (mode == 0) {
                if (zout) zout[b * CN + c] = z;
                la1 += z * z;
            } else if (mode == 1) {
                zout[b * CN + c] = z;
                float xc = g_vec[0][b * CN + c] * invu4;
                la1 += z * xc; la2 += xc * xc;
            } else {
                float xc = g_vec[2][b * CN + c];
                la1 += z * xc; la2 += xc * xc;
            }
        }
        if (r < 7) {
            #pragma unroll
            for (int k = 0; k < 7; k++) cur[k] = nxt[k];
        }
    }

    // --- warp partials -> block sum -> Yout ---
    if (youtSel >= 0) {
        float4* yo = (float4*)yw[warp];
        #pragma unroll
        for (int k = 0; k < 6; k++) yo[k * 32 + lane] = acc[k];
        if (k6) yo[192 + lane] = acc[6];
    }
    if (lane == 0) { r1s[warp] = la1; r2s[warp] = la2; }
    __syncthreads();
    if (youtSel >= 0) {
        float* Yout = youtSel ? g_Yb : g_Ya;
        for (int i = t; i < HW; i += 256) {
            float s = 0.f;
            #pragma unroll
            for (int w = 0; w < 8; w++) s += yw[w][i];
            Yout[(seg * BN + b) * HW + i] = s;
        }
    }
    if (t == 0) {
        float s1 = 0.f, s2 = 0.f;
        #pragma unroll
        for (int w = 0; w < 8; w++) { s1 += r1s[w]; s2 += r2s[w]; }
        if (mode == 0) {
            atomicAdd(&g_nrm2[a1][b], s1);
        } else {
            atomicAdd(&g_sc[a1][b], s1);
            atomicAdd(&g_sc[a2][b], s2);
        }
    }
}

// ---------------- K5: largest, w = v - largest*x1, x2 = w/||w||, invw --------
__global__ void k_k5() {
    __shared__ float red[16];
    __shared__ float wtot;
    int b = blockIdx.x, t = threadIdx.x;       // 512 threads
    float inv4 = 1.0f / fmaxf(sqrtf(g_nrm2[4][b]), FEPS);
    float largest = g_sc[0][b] / g_sc[1][b];
    float x1c = g_vec[0][b * CN + t] * inv4;
    float w = g_vec[1][b * CN + t] - largest * x1c;
    float s = w * w;
    #pragma unroll
    for (int o = 16; o; o >>= 1) s += __shfl_xor_sync(0xffffffffu, s, o);
    if ((t & 31) == 0) red[t >> 5] = s;
    __syncthreads();
    if (t < 16) {
        s = red[t];
        #pragma unroll
        for (int o = 8; o; o >>= 1) s += __shfl_xor_sync(0xffffu, s, o);
        if (t == 0) wtot = s;
    }
    __syncthreads();
    float invw = 1.0f / fmaxf(sqrtf(wtot), FEPS);
    g_vec[2][b * CN + t] = w * invw;
    if (t == 0) { g_sc[4][b] = largest; g_sc[5][b] = invw; }
}

// ---------------- final: penalty = sum_b (largest/smallest - 1)^2 / B --------
__global__ void k_fin(float* __restrict__ out) {
    __shared__ float red[2];
    int t = threadIdx.x;                        // 64 threads
    float largest = g_sc[4][t];
    float tmp = g_sc[2][t] / g_sc[3][t] - largest;
    float smallest = tmp + largest;
    float r = largest / smallest - 1.0f;
    float p = r * r;
    #pragma unroll
    for (int o = 16; o; o >>= 1) p += __shfl_xor_sync(0xffffffffu, p, o);
    if ((t & 31) == 0) red[t >> 5] = p;
    __syncthreads();
    if (t == 0) out[0] = (red[0] + red[1]) / (float)BN;
}

// ---------------- launch ----------------
extern "C" void kernel_launch(void* const* d_in, const int* in_sizes, int n_in,
                              void* d_out, int out_size) {
    const float* A  = (const float*)d_in[0];
    const float* x0 = (const float*)d_in[1];
    if (n_in >= 2 && in_sizes[0] < in_sizes[1]) {   // safety: A is the big one
        const float* t = A; A = x0; x0 = t;
    }
    const float4* A4 = (const float4*)A;
    float* out = (float*)d_out;
    (void)out_size;

    k_init<<<1, 512>>>();
    k_n0<<<BN, CN>>>(x0);

    // Y0 = Wm^T x0 (unnormalized) -> g_Ya          [1 A-sweep, establishes L2 residency]
    k_s1<<<BN * NSEG, 224>>>(A4, x0);

    // applies 1..4: z_k = AAT x_{k-1}hat, fused Ynext   [4 A-sweeps]
    k_ap<<<BN * NSEG, 256>>>(A4, 0, 1, -1, 0, 0, 1, 0);   // z1, Y1->Yb
    k_ap<<<BN * NSEG, 256>>>(A4, 1, 0, -1, 0, 1, 2, 0);   // z2, Y2->Ya
    k_ap<<<BN * NSEG, 256>>>(A4, 0, 1, -1, 0, 2, 3, 0);   // z3, Y3->Yb
    k_ap<<<BN * NSEG, 256>>>(A4, 1, 0,  0, 0, 3, 4, 0);   // z4=u4 store, Y4->Ya

    // apply 5: v = AAT x1; num5=v.x1, den5=||x1||^2; Y5->Yb   [1 A-sweep]
    k_ap<<<BN * NSEG, 256>>>(A4, 0, 1,  1, 1, 4, 0, 1);

    // largest, x2, invw
    k_k5<<<BN, CN>>>();

    // apply 6: t = AAT x2 (ys from Y4,Y5 combo); num6, den6   [1 A-sweep]
    k_ap<<<BN * NSEG, 256>>>(A4, 0, -1, -1, 2, 0, 2, 3);

    k_fin<<<1, 64>>>(out);
}

// round 7
// speedup vs baseline: 1.6532x; 1.1464x over previous
#include <cuda_runtime.h>
#include <math.h>

#define BN 64
#define CN 512
#define HW 784
#define HW4 196
#define NSEG 8
#define CSEG 64
#define FEPS 1e-12f

// ---------------- scratch (static __device__, no allocation) ----------------
__device__ float g_Ya[NSEG * BN * HW];    // ping: Y0, Y2, Y4 (= Wm^T z, unnormalized, seg partials)
__device__ float g_Yb[NSEG * BN * HW];    // pong: Y1, Y3, Y5
__device__ float g_u4[BN * CN];           // z4 (raw, pre-normalization)
__device__ float g_ysum[BN * HW];         // summed Y4 (built by k_mid)
__device__ float g_nrm2[8][BN];           // 0:||x0||^2, 1..4:||z_k||^2
__device__ float g_sc[8][BN];             // 0:largest 1:||w||^2 2:pen_b 3:invu4

// L2 evict_last policy for A loads (103MB vs 126MB L2)
__device__ __forceinline__ unsigned long long mk_policy() {
    unsigned long long pol;
    asm("createpolicy.fractional.L2::evict_last.b64 %0, 1.0;" : "=l"(pol));
    return pol;
}
__device__ __forceinline__ float4 ldg_el(const float4* p, unsigned long long pol) {
    float4 r;
    asm volatile("ld.global.nc.L2::cache_hint.v4.f32 {%0,%1,%2,%3}, [%4], %5;"
                 : "=f"(r.x), "=f"(r.y), "=f"(r.z), "=f"(r.w) : "l"(p), "l"(pol));
    return r;
}

// ---------------- init: zero accumulators ----------------
__global__ void k_init() {
    int t = threadIdx.x;                       // 512 threads
    if (t < 8 * BN) ((float*)g_nrm2)[t] = 0.0f;
    if (t < 8 * BN) ((float*)g_sc)[t] = 0.0f;
}

// ---------------- ||x0||^2 per batch ----------------
__global__ void k_n0(const float* __restrict__ x0) {
    __shared__ float red[16];
    int b = blockIdx.x, t = threadIdx.x;       // 512 threads = C
    float v = x0[b * CN + t];
    float s = v * v;
    #pragma unroll
    for (int o = 16; o; o >>= 1) s += __shfl_xor_sync(0xffffffffu, s, o);
    if ((t & 31) == 0) red[t >> 5] = s;
    __syncthreads();
    if (t < 16) {
        s = red[t];
        #pragma unroll
        for (int o = 8; o; o >>= 1) s += __shfl_xor_sync(0xffffu, s, o);
        if (t == 0) g_nrm2[0][b] = s;
    }
}

// ---------------- S1: Y0[seg][b][d] = sum_{c in seg} A[b][c][d]*x0[b][c] ----
__global__ void k_s1(const float4* __restrict__ A4, const float* __restrict__ x0in) {
    int b = blockIdx.x >> 3, seg = blockIdx.x & 7;
    int t = threadIdx.x;                       // 224 threads, 196 active
    if (t >= HW4) return;
    unsigned long long pol = mk_policy();
    const float* xp = x0in + b * CN + seg * CSEG;
    const float4* Ab = A4 + (size_t)(b * CN + seg * CSEG) * HW4 + t;
    float ax = 0.f, ay = 0.f, az = 0.f, aw = 0.f;
    #pragma unroll 8
    for (int c = 0; c < CSEG; c++) {
        float xv = xp[c];
        float4 a = ldg_el(Ab + (size_t)c * HW4, pol);
        ax += a.x * xv; ay += a.y * xv; az += a.z * xv; aw += a.w * xv;
    }
    float4 r; r.x = ax; r.y = ay; r.z = az; r.w = aw;
    ((float4*)g_Ya)[(seg * BN + b) * HW4 + t] = r;
}

// ---------------- fused apply: z = Wm*ys ; Ynext = Wm^T z ; reductions ------
// mode 0: ys = sum(Yin segs) * rsqrt(nrm2[nsIn]); reduce ||z||^2 -> nrm2[a1];
//         optionally store z -> g_u4 (storeZ)
// mode 1: ys = g_ysum * invu4 (z = v = AAT x1); per-row w = z - largest*x1_c;
//         reduce ||w||^2 -> g_sc[1]; Yout = Y5
__global__ void __launch_bounds__(256, 2) k_ap(
        const float4* __restrict__ A4, int yinSel, int youtSel,
        int mode, int nsIn, int a1, int storeZ)
{
    __shared__ float ys[HW];
    __shared__ float yw[8][HW];
    __shared__ float r1s[8];
    int b = blockIdx.x >> 3, seg = blockIdx.x & 7;
    int t = threadIdx.x, warp = t >> 5, lane = t & 31;   // 256 threads
    unsigned long long pol = mk_policy();

    float largest = 0.f, invu4 = 1.f;
    if (mode == 1) { largest = g_sc[0][b]; invu4 = g_sc[3][b]; }

    // --- build ys in shared ---
    if (mode == 0) {
        const float* Yin = yinSel ? g_Yb : g_Ya;
        float s = 1.0f / fmaxf(sqrtf(g_nrm2[nsIn][b]), FEPS);
        for (int i = t; i < HW; i += 256) {
            float acc = 0.f;
            #pragma unroll
            for (int sg = 0; sg < NSEG; sg++) acc += Yin[(sg * BN + b) * HW + i];
            ys[i] = acc * s;
        }
    } else {
        for (int i = t; i < HW; i += 256) ys[i] = g_ysum[b * HW + i] * invu4;
    }
    __syncthreads();

    const float4* ys4 = (const float4*)ys;
    bool k6 = (lane < 4);
    float4 acc[7];
    #pragma unroll
    for (int k = 0; k < 7; k++) acc[k] = make_float4(0.f, 0.f, 0.f, 0.f);
    float la1 = 0.f;

    int c0 = seg * CSEG + warp * 8;
    const float4* Ar0 = A4 + (size_t)(b * CN + c0) * HW4;

    // --- software-pipelined rows: cur/nxt double buffer (MLP ~14/warp) ---
    float4 cur[7], nxt[7];
    #pragma unroll
    for (int k = 0; k < 6; k++) cur[k] = ldg_el(Ar0 + k * 32 + lane, pol);
    cur[6] = k6 ? ldg_el(Ar0 + 192 + lane, pol) : make_float4(0.f, 0.f, 0.f, 0.f);

    #pragma unroll
    for (int r = 0; r < 8; r++) {
        if (r < 7) {
            const float4* Arn = Ar0 + (size_t)(r + 1) * HW4;
            #pragma unroll
            for (int k = 0; k < 6; k++) nxt[k] = ldg_el(Arn + k * 32 + lane, pol);
            nxt[6] = k6 ? ldg_el(Arn + 192 + lane, pol) : make_float4(0.f, 0.f, 0.f, 0.f);
        }
        float d0 = 0.f, d1 = 0.f, d2 = 0.f, d3 = 0.f;
        #pragma unroll
        for (int k = 0; k < 6; k++) {
            float4 y = ys4[k * 32 + lane];
            d0 += cur[k].x * y.x; d1 += cur[k].y * y.y;
            d2 += cur[k].z * y.z; d3 += cur[k].w * y.w;
        }
        if (k6) {
            float4 y = ys4[192 + lane];
            d0 += cur[6].x * y.x; d1 += cur[6].y * y.y;
            d2 += cur[6].z * y.z; d3 += cur[6].w * y.w;
        }
        float z = (d0 + d1) + (d2 + d3);
        #pragma unroll
        for (int o = 16; o; o >>= 1) z += __shfl_xor_sync(0xffffffffu, z, o);

        // axpy into Ynext accumulators (row still in registers)
        #pragma unroll
        for (int k = 0; k < 7; k++) {
            acc[k].x += z * cur[k].x; acc[k].y += z * cur[k].y;
            acc[k].z += z * cur[k].z; acc[k].w += z * cur[k].w;
        }
        if (lane == 0) {
            int c = c0 + r;
            if (mode == 0) {
                if (storeZ) g_u4[b * CN + c] = z;
                la1 += z * z;
            } else {
                float w = z - largest * (g_u4[b * CN + c] * invu4);
                la1 += w * w;
            }
        }
        if (r < 7) {
            #pragma unroll
            for (int k = 0; k < 7; k++) cur[k] = nxt[k];
        }
    }

    // --- warp partials -> block sum -> Yout ---
    if (youtSel >= 0) {
        float4* yo = (float4*)yw[warp];
        #pragma unroll
        for (int k = 0; k < 6; k++) yo[k * 32 + lane] = acc[k];
        if (k6) yo[192 + lane] = acc[6];
    }
    if (lane == 0) r1s[warp] = la1;
    __syncthreads();
    if (youtSel >= 0) {
        float* Yout = youtSel ? g_Yb : g_Ya;
        for (int i = t; i < HW; i += 256) {
            float s = 0.f;
            #pragma unroll
            for (int w = 0; w < 8; w++) s += yw[w][i];
            Yout[(seg * BN + b) * HW + i] = s;
        }
    }
    if (t == 0) {
        float s1 = 0.f;
        #pragma unroll
        for (int w = 0; w < 8; w++) s1 += r1s[w];
        if (mode == 0) atomicAdd(&g_nrm2[a1][b], s1);
        else           atomicAdd(&g_sc[1][b], s1);
    }
}

// ---------------- mid: ysum = sum(Y4 segs); largest = ||Y4||^2/||z4||^2 -----
__global__ void k_mid() {
    __shared__ float red[8];
    int b = blockIdx.x, t = threadIdx.x, warp = t >> 5, lane = t & 31;  // 256 thr
    float loc = 0.f;
    for (int i = t; i < HW; i += 256) {
        float s = 0.f;
        #pragma unroll
        for (int sg = 0; sg < NSEG; sg++) s += g_Ya[(sg * BN + b) * HW + i];
        g_ysum[b * HW + i] = s;
        loc += s * s;
    }
    #pragma unroll
    for (int o = 16; o; o >>= 1) loc += __shfl_xor_sync(0xffffffffu, loc, o);
    if (lane == 0) red[warp] = loc;
    __syncthreads();
    if (t == 0) {
        float tot = 0.f;
        #pragma unroll
        for (int w = 0; w < 8; w++) tot += red[w];
        float invu4 = 1.0f / fmaxf(sqrtf(g_nrm2[4][b]), FEPS);
        g_sc[3][b] = invu4;
        g_sc[0][b] = tot * invu4 * invu4;   // largest = ||W^T x1||^2
    }
}

// ---------------- pen: y6 = sum(Y5) - largest*invu4*ysum; per-batch penalty --
__global__ void k_pen() {
    __shared__ float red[8];
    int b = blockIdx.x, t = threadIdx.x, warp = t >> 5, lane = t & 31;  // 256 thr
    float largest = g_sc[0][b], invu4 = g_sc[3][b];
    float f = largest * invu4;
    float loc = 0.f;
    for (int i = t; i < HW; i += 256) {
        float s = 0.f;
        #pragma unroll
        for (int sg = 0; sg < NSEG; sg++) s += g_Yb[(sg * BN + b) * HW + i];
        float y6 = s - f * g_ysum[b * HW + i];   // W^T w (w-basis, scale-invariant)
        loc += y6 * y6;
    }
    #pragma unroll
    for (int o = 16; o; o >>= 1) loc += __shfl_xor_sync(0xffffffffu, loc, o);
    if (lane == 0) red[warp] = loc;
    __syncthreads();
    if (t == 0) {
        float num6 = 0.f;
        #pragma unroll
        for (int w = 0; w < 8; w++) num6 += red[w];
        float smallest = num6 / g_sc[1][b];      // ||W^T w||^2 / ||w||^2
        float r = largest / smallest - 1.0f;
        g_sc[2][b] = r * r;
    }
}

// ---------------- final: sum penalties / B ----------------
__global__ void k_sum(float* __restrict__ out) {
    __shared__ float red[2];
    int t = threadIdx.x;                        // 64 threads
    float p = g_sc[2][t];
    #pragma unroll
    for (int o = 16; o; o >>= 1) p += __shfl_xor_sync(0xffffffffu, p, o);
    if ((t & 31) == 0) red[t >> 5] = p;
    __syncthreads();
    if (t == 0) out[0] = (red[0] + red[1]) / (float)BN;
}

// ---------------- launch ----------------
extern "C" void kernel_launch(void* const* d_in, const int* in_sizes, int n_in,
                              void* d_out, int out_size) {
    const float* A  = (const float*)d_in[0];
    const float* x0 = (const float*)d_in[1];
    if (n_in >= 2 && in_sizes[0] < in_sizes[1]) {   // safety: A is the big one
        const float* t = A; A = x0; x0 = t;
    }
    const float4* A4 = (const float4*)A;
    float* out = (float*)d_out;
    (void)out_size;

    k_init<<<1, 512>>>();
    k_n0<<<BN, CN>>>(x0);

    // Y0 = Wm^T x0 -> g_Ya                               [sweep 1]
    k_s1<<<BN * NSEG, 224>>>(A4, x0);

    //                       in out mode ns a1 stZ
    k_ap<<<BN * NSEG, 256>>>(A4, 0, 1, 0, 0, 1, 0);   // z1, Y1->Yb   [sweep 2]
    k_ap<<<BN * NSEG, 256>>>(A4, 1, 0, 0, 1, 2, 0);   // z2, Y2->Ya   [sweep 3]
    k_ap<<<BN * NSEG, 256>>>(A4, 0, 1, 0, 2, 3, 0);   // z3, Y3->Yb   [sweep 4]
    k_ap<<<BN * NSEG, 256>>>(A4, 1, 0, 0, 3, 4, 1);   // z4->u4, Y4->Ya [sweep 5]

    k_mid<<<BN, 256>>>();                             // ysum, largest, invu4

    // v = AAT x1; ||w||^2; Y5->Yb                        [sweep 6]
    k_ap<<<BN * NSEG, 256>>>(A4, 0, 1, 1, 4, 1, 0);

    k_pen<<<BN, 256>>>();                             // per-batch penalty
    k_sum<<<1, 64>>>(out);
}